// round 8
// baseline (speedup 1.0000x reference)
#include <cuda_runtime.h>
#include <math.h>
#include <stdint.h>

// Problem dims
#define Bdim   4
#define Sdim   2048
#define DMdim  1024
#define Hdim   16
#define DPT    64
#define BHdim  (Bdim*Hdim)

#define OUT_ELEMS  (Bdim*Sdim*DMdim)                 // 8388608
#define ATTN_ELEMS ((long long)BHdim*Sdim*Sdim)      // 268435456
#define CHUNK_BH   4
#define NCTILE     16                                 // Sdim/128 col tiles

// Scratch (allocation-free: __device__ globals). ~206 MB total.
__device__ float g_qh[(size_t)BHdim*Sdim*DPT];
__device__ float g_kh[(size_t)BHdim*Sdim*DPT];
__device__ float g_vh[(size_t)BHdim*Sdim*DPT];
__device__ float g_concat[(size_t)Bdim*Sdim*DMdim];
__device__ float g_psum[(size_t)BHdim*Sdim*NCTILE];  // per-(row, col-tile) exp sums
__device__ float g_attn_chunk[(size_t)CHUNK_BH*Sdim*Sdim];

// ---------------------------------------------------------------------------
__device__ __forceinline__ uint32_t f2tf(float x) {
    uint32_t r;
    asm("cvt.rna.tf32.f32 %0, %1;" : "=r"(r) : "f"(x));
    return r;
}

__device__ __forceinline__ void mma8(float* c, const uint32_t* a, const uint32_t* b) {
    asm volatile(
        "mma.sync.aligned.m16n8k8.row.col.f32.tf32.tf32.f32 "
        "{%0,%1,%2,%3},{%4,%5,%6,%7},{%8,%9},{%0,%1,%2,%3};\n"
        : "+f"(c[0]), "+f"(c[1]), "+f"(c[2]), "+f"(c[3])
        : "r"(a[0]), "r"(a[1]), "r"(a[2]), "r"(a[3]), "r"(b[0]), "r"(b[1]));
}

// Fragment-major staging.
// A value (row, k): mtile=row>>4, r=row&7, rh=(row>>3)&1; ks=k>>3, q=k&3,
// kh=(k>>2)&1; lane idx = 4r+((q+r)&3); reg = rh+2*kh.
// Block stride: 128 u32 per (ks,mtile). Lane holds 4 contiguous regs (LDS.128).
__device__ __forceinline__ void stageA(uint32_t* Asm, int row, int c, float4 v) {
    int ks = c >> 3, kh = (c >> 2) & 1;
    int mt = row >> 4, rr = row & 7, rh = (row >> 3) & 1;
    int reg = rh + 2 * kh;
    uint32_t* base = Asm + (((ks << 3) + mt) << 7) + reg;
    base[(4*rr + ((0 + rr) & 3)) * 4] = f2tf(v.x);
    base[(4*rr + ((1 + rr) & 3)) * 4] = f2tf(v.y);
    base[(4*rr + ((2 + rr) & 3)) * 4] = f2tf(v.z);
    base[(4*rr + ((3 + rr) & 3)) * 4] = f2tf(v.w);
}

// B value (n, k): ntile=n>>3, r=n&7; ks=k>>3, q=k&3, kh=(k>>2)&1;
// lane idx = 4r+((q+r)&3); reg = kh. Block stride 64 u32 per (ks,ntile).
__device__ __forceinline__ void stageB(uint32_t* Bsm, int n, int c, float4 v) {
    int ks = c >> 3, kh = (c >> 2) & 1;
    int nt = n >> 3, rr = n & 7;
    uint32_t* base = Bsm + (((ks << 4) + nt) << 6) + kh;
    base[(4*rr + ((0 + rr) & 3)) * 2] = f2tf(v.x);
    base[(4*rr + ((1 + rr) & 3)) * 2] = f2tf(v.y);
    base[(4*rr + ((2 + rr) & 3)) * 2] = f2tf(v.z);
    base[(4*rr + ((3 + rr) & 3)) * 2] = f2tf(v.w);
}

// ---------------------------------------------------------------------------
// tf32 GEMM: C(128x128/block) = A(MxK) @ W(NxK)^T (+bias), K=1024, BK=16
// EPI: 0 = dense row-major (M x DMdim), 1 = head-scatter to (B,H,S,DPT)
// ---------------------------------------------------------------------------
template<int EPI>
__global__ void __launch_bounds__(256, 2)
gemm1024_tf32(const float* __restrict__ A, const float* __restrict__ W,
              const float* __restrict__ bias, float* __restrict__ out)
{
    const int K = 1024;
    __shared__ uint32_t Asm[2*8*128];    // 8 KB
    __shared__ uint32_t Bsm[2*16*64];    // 8 KB
    int t = threadIdx.x, lane = t & 31, w = t >> 5;
    int q = lane & 3, r = lane >> 2;
    int m0 = blockIdx.y * 128, n0 = blockIdx.x * 128;
    int wm = (w & 1) * 64, wn = (w >> 1) * 32;
    int mtb = wm >> 4, ntb = wn >> 3;
    int lr = t >> 1, lc = (t & 1) * 4;
    const float* Ap = A + (size_t)(m0 + lr) * K + lc;
    const float* Wp = W + (size_t)(n0 + lr) * K + lc;
    int idx = 4*r + ((q + r) & 3);

    float acc[4][4][4];
    #pragma unroll
    for (int i = 0; i < 4; i++)
        #pragma unroll
        for (int j = 0; j < 4; j++)
            #pragma unroll
            for (int v = 0; v < 4; v++) acc[i][j][v] = 0.f;

    float4 pa0 = *(const float4*)Ap,      pa1 = *(const float4*)(Ap + 8);
    float4 pb0 = *(const float4*)Wp,      pb1 = *(const float4*)(Wp + 8);

    for (int kt = 0; kt < K; kt += 16) {
        __syncthreads();
        stageA(Asm, lr, lc,     pa0);
        stageA(Asm, lr, lc + 8, pa1);
        stageB(Bsm, lr, lc,     pb0);
        stageB(Bsm, lr, lc + 8, pb1);
        __syncthreads();
        if (kt + 16 < K) {
            pa0 = *(const float4*)(Ap + kt + 16); pa1 = *(const float4*)(Ap + kt + 24);
            pb0 = *(const float4*)(Wp + kt + 16); pb1 = *(const float4*)(Wp + kt + 24);
        }
        #pragma unroll
        for (int ks = 0; ks < 2; ks++) {
            uint4 af[4]; uint2 bf[4];
            #pragma unroll
            for (int mt = 0; mt < 4; mt++)
                af[mt] = *(const uint4*)&Asm[(((ks << 3) + mtb + mt) << 7) + idx*4];
            #pragma unroll
            for (int nt = 0; nt < 4; nt++)
                bf[nt] = *(const uint2*)&Bsm[(((ks << 4) + ntb + nt) << 6) + idx*2];
            #pragma unroll
            for (int mt = 0; mt < 4; mt++)
                #pragma unroll
                for (int nt = 0; nt < 4; nt++)
                    mma8(acc[mt][nt], (const uint32_t*)&af[mt], (const uint32_t*)&bf[nt]);
        }
    }

    #pragma unroll
    for (int mt = 0; mt < 4; mt++) {
        #pragma unroll
        for (int nt = 0; nt < 4; nt++) {
            int m = m0 + wm + mt*16 + r;
            int n = n0 + wn + nt*8 + 2*q;
            float* a4 = acc[mt][nt];
            float bv0 = bias[n], bv1 = bias[n+1];
            if (EPI == 0) {
                *(float2*)&out[(size_t)m*DMdim + n]     = make_float2(a4[0]+bv0, a4[1]+bv1);
                *(float2*)&out[(size_t)(m+8)*DMdim + n] = make_float2(a4[2]+bv0, a4[3]+bv1);
            } else {
                int bb = m >> 11, s = m & 2047, h = n >> 6, d = n & 63;
                size_t base = ((size_t)(bb*Hdim + h)) * Sdim;
                *(float2*)&out[(base + s)*DPT + d]     = make_float2(a4[0]+bv0, a4[1]+bv1);
                *(float2*)&out[(base + s + 8)*DPT + d] = make_float2(a4[2]+bv0, a4[3]+bv1);
            }
        }
    }
}

// ---------------------------------------------------------------------------
// QK^T (tf32) + fused exp: P = exp(Q@K^T * 0.125 + mask*(-1e9))
// Writes unnormalized P to attn and per-(row, col-tile) sums to g_psum.
// ---------------------------------------------------------------------------
__global__ void __launch_bounds__(256, 2)
qk_tf32(const float* __restrict__ mask, float* __restrict__ attn, int bh_base)
{
    const int K = DPT;
    __shared__ uint32_t Asm[2*8*128];
    __shared__ uint32_t Bsm[2*16*64];
    __shared__ float sred[128][4];
    int t = threadIdx.x, lane = t & 31, w = t >> 5;
    int q = lane & 3, r = lane >> 2;
    int zl = blockIdx.z, bh = bh_base + zl;
    int m0 = blockIdx.y * 128, n0 = blockIdx.x * 128;
    int wm = (w & 1) * 64, wn = (w >> 1) * 32;
    int mtb = wm >> 4, ntb = wn >> 3;
    int wnidx = w >> 1;
    int lr = t >> 1, lc = (t & 1) * 4;
    const float* Q  = g_qh + (size_t)bh * Sdim * DPT;
    const float* Kh = g_kh + (size_t)bh * Sdim * DPT;
    const float* Ap = Q  + (size_t)(m0 + lr) * K + lc;
    const float* Wp = Kh + (size_t)(n0 + lr) * K + lc;
    int idx = 4*r + ((q + r) & 3);

    float acc[4][4][4];
    #pragma unroll
    for (int i = 0; i < 4; i++)
        #pragma unroll
        for (int j = 0; j < 4; j++)
            #pragma unroll
            for (int v = 0; v < 4; v++) acc[i][j][v] = 0.f;

    float4 pa0 = *(const float4*)Ap, pa1 = *(const float4*)(Ap + 8);
    float4 pb0 = *(const float4*)Wp, pb1 = *(const float4*)(Wp + 8);

    #pragma unroll
    for (int kt = 0; kt < K; kt += 16) {
        __syncthreads();
        stageA(Asm, lr, lc,     pa0);
        stageA(Asm, lr, lc + 8, pa1);
        stageB(Bsm, lr, lc,     pb0);
        stageB(Bsm, lr, lc + 8, pb1);
        __syncthreads();
        if (kt + 16 < K) {
            pa0 = *(const float4*)(Ap + kt + 16); pa1 = *(const float4*)(Ap + kt + 24);
            pb0 = *(const float4*)(Wp + kt + 16); pb1 = *(const float4*)(Wp + kt + 24);
        }
        #pragma unroll
        for (int ks = 0; ks < 2; ks++) {
            uint4 af[4]; uint2 bf[4];
            #pragma unroll
            for (int mt = 0; mt < 4; mt++)
                af[mt] = *(const uint4*)&Asm[(((ks << 3) + mtb + mt) << 7) + idx*4];
            #pragma unroll
            for (int nt = 0; nt < 4; nt++)
                bf[nt] = *(const uint2*)&Bsm[(((ks << 4) + ntb + nt) << 6) + idx*2];
            #pragma unroll
            for (int mt = 0; mt < 4; mt++)
                #pragma unroll
                for (int nt = 0; nt < 4; nt++)
                    mma8(acc[mt][nt], (const uint32_t*)&af[mt], (const uint32_t*)&bf[nt]);
        }
    }

    const float* mrow = mask + (size_t)(bh >> 4) * Sdim;
    float* orow = attn + (size_t)zl * Sdim * Sdim;
    float rsum[8];
    #pragma unroll
    for (int i = 0; i < 8; i++) rsum[i] = 0.f;

    #pragma unroll
    for (int mt = 0; mt < 4; mt++) {
        #pragma unroll
        for (int nt = 0; nt < 4; nt++) {
            int m = m0 + wm + mt*16 + r;
            int n = n0 + wn + nt*8 + 2*q;
            float* a4 = acc[mt][nt];
            float mk0 = mrow[n] * (-1e9f), mk1 = mrow[n+1] * (-1e9f);
            float p0 = __expf(a4[0]*0.125f + mk0);
            float p1 = __expf(a4[1]*0.125f + mk1);
            float p2 = __expf(a4[2]*0.125f + mk0);
            float p3 = __expf(a4[3]*0.125f + mk1);
            *(float2*)&orow[(size_t)m*Sdim + n]     = make_float2(p0, p1);
            *(float2*)&orow[(size_t)(m+8)*Sdim + n] = make_float2(p2, p3);
            rsum[mt*2+0] += p0 + p1;
            rsum[mt*2+1] += p2 + p3;
        }
    }
    #pragma unroll
    for (int i = 0; i < 8; i++) {
        rsum[i] += __shfl_xor_sync(0xffffffffu, rsum[i], 1);
        rsum[i] += __shfl_xor_sync(0xffffffffu, rsum[i], 2);
    }
    if (q == 0) {
        #pragma unroll
        for (int mt = 0; mt < 4; mt++) {
            sred[wm + mt*16 + r][wnidx]     = rsum[mt*2+0];
            sred[wm + mt*16 + 8 + r][wnidx] = rsum[mt*2+1];
        }
    }
    __syncthreads();
    if (t < 128) {
        float s = sred[t][0] + sred[t][1] + sred[t][2] + sred[t][3];
        g_psum[((size_t)bh * Sdim + m0 + t) * NCTILE + blockIdx.x] = s;
    }
}

// ---------------------------------------------------------------------------
// PV (tf32) + fused normalize: BK=32; normalized P written back to attn in
// place; ctx = Pn @ V into g_concat (B,S,DM) head-interleaved.
// ---------------------------------------------------------------------------
__global__ void __launch_bounds__(256, 2)
pv_tf32(float* __restrict__ attn, int bh_base)
{
    __shared__ uint32_t Psm[4*8*128];    // 16 KB
    __shared__ uint32_t Vsm[4*8*64];     // 8 KB
    __shared__ float sinv[128];
    int t = threadIdx.x, lane = t & 31, w = t >> 5;
    int q = lane & 3, r = lane >> 2;
    int zl = blockIdx.y, bh = bh_base + zl;
    int m0 = blockIdx.x * 128;
    int wm = (w & 3) * 32, wn = (w >> 2) * 32;
    int mtb = wm >> 4, ntb = wn >> 3;
    float* P = attn + (size_t)zl * Sdim * Sdim;
    const float* V = g_vh + (size_t)bh * Sdim * DPT;
    int idx = 4*r + ((q + r) & 3);

    if (t < 128) {
        const float* pp = &g_psum[((size_t)bh * Sdim + m0 + t) * NCTILE];
        float s = 0.f;
        #pragma unroll
        for (int i = 0; i < NCTILE; i++) s += pp[i];
        sinv[t] = 1.0f / s;
    }
    __syncthreads();

    int lr = t >> 1, lc = (t & 1) * 16;
    float* Pp = P + (size_t)(m0 + lr) * Sdim + lc;
    int vr = t >> 3, vc = (t & 7) * 8;
    const float* Vp = V + (size_t)vr * DPT + vc;
    float inv_r = sinv[lr];

    float acc[2][4][4];
    #pragma unroll
    for (int i = 0; i < 2; i++)
        #pragma unroll
        for (int j = 0; j < 4; j++)
            #pragma unroll
            for (int v = 0; v < 4; v++) acc[i][j][v] = 0.f;

    float4 pa[4];
    #pragma unroll
    for (int i = 0; i < 4; i++) pa[i] = *(const float4*)(Pp + 4*i);
    float4 pv0 = *(const float4*)(Vp);
    float4 pv1 = *(const float4*)(Vp + 4);

    for (int kt = 0; kt < Sdim; kt += 32) {
        float4 sa[4];
        #pragma unroll
        for (int i = 0; i < 4; i++) {
            sa[i].x = pa[i].x * inv_r; sa[i].y = pa[i].y * inv_r;
            sa[i].z = pa[i].z * inv_r; sa[i].w = pa[i].w * inv_r;
        }
        #pragma unroll
        for (int i = 0; i < 4; i++)
            *(float4*)(Pp + kt + 4*i) = sa[i];

        __syncthreads();
        #pragma unroll
        for (int i = 0; i < 4; i++)
            stageA(Psm, lr, lc + 4*i, sa[i]);
        // V staging: k-row vr (0..31), cols vc..vc+7
        {
            int ks = vr >> 3, kh = (vr >> 2) & 1;
            int qb = vr & 3;
            int ntv = vc >> 3;
            uint32_t* base = Vsm + (((ks << 3) + ntv) << 6) + kh;
            const float* vv = (const float*)&pv0;
            #pragma unroll
            for (int i = 0; i < 4; i++)
                base[(4*i + ((qb + i) & 3)) * 2] = f2tf(vv[i]);
            const float* vv1 = (const float*)&pv1;
            #pragma unroll
            for (int i = 0; i < 4; i++)
                base[(4*(i+4) + ((qb + i + 4) & 3)) * 2] = f2tf(vv1[i]);
        }
        __syncthreads();
        if (kt + 32 < Sdim) {
            #pragma unroll
            for (int i = 0; i < 4; i++) pa[i] = *(const float4*)(Pp + kt + 32 + 4*i);
            pv0 = *(const float4*)(Vp + (size_t)(kt + 32) * DPT);
            pv1 = *(const float4*)(Vp + (size_t)(kt + 32) * DPT + 4);
        }
        #pragma unroll
        for (int ks = 0; ks < 4; ks++) {
            uint4 af[2]; uint2 bf[4];
            #pragma unroll
            for (int mt = 0; mt < 2; mt++)
                af[mt] = *(const uint4*)&Psm[(((ks << 3) + mtb + mt) << 7) + idx*4];
            #pragma unroll
            for (int nt = 0; nt < 4; nt++)
                bf[nt] = *(const uint2*)&Vsm[(((ks << 3) + ntb + nt) << 6) + idx*2];
            #pragma unroll
            for (int mt = 0; mt < 2; mt++)
                #pragma unroll
                for (int nt = 0; nt < 4; nt++)
                    mma8(acc[mt][nt], (const uint32_t*)&af[mt], (const uint32_t*)&bf[nt]);
        }
    }

    int bb = bh >> 4, h = bh & 15;
    #pragma unroll
    for (int mt = 0; mt < 2; mt++) {
        #pragma unroll
        for (int nt = 0; nt < 4; nt++) {
            int s = m0 + wm + mt*16 + r;
            int dcol = wn + nt*8 + 2*q;
            float* a4 = acc[mt][nt];
            size_t base = ((size_t)bb * Sdim + s) * DMdim + h*DPT + dcol;
            *(float2*)&g_concat[base]            = make_float2(a4[0], a4[1]);
            *(float2*)&g_concat[base + 8*DMdim]  = make_float2(a4[2], a4[3]);
        }
    }
}

// ---------------------------------------------------------------------------
extern "C" void kernel_launch(void* const* d_in, const int* in_sizes, int n_in,
                              void* d_out, int out_size)
{
    const float* v_in    = (const float*)d_in[0];
    const float* k_in    = (const float*)d_in[1];
    const float* q_in    = (const float*)d_in[2];
    const float* mask    = (const float*)d_in[3];
    const float* wq_w    = (const float*)d_in[4];
    const float* wq_b    = (const float*)d_in[5];
    const float* wk_w    = (const float*)d_in[6];
    const float* wk_b    = (const float*)d_in[7];
    const float* wv_w    = (const float*)d_in[8];
    const float* wv_b    = (const float*)d_in[9];
    const float* dense_w = (const float*)d_in[10];
    const float* dense_b = (const float*)d_in[11];

    float *qh, *kh, *vh, *concat, *attn_chunk;
    cudaGetSymbolAddress((void**)&qh, g_qh);
    cudaGetSymbolAddress((void**)&kh, g_kh);
    cudaGetSymbolAddress((void**)&vh, g_vh);
    cudaGetSymbolAddress((void**)&concat, g_concat);
    cudaGetSymbolAddress((void**)&attn_chunk, g_attn_chunk);

    float* out = (float*)d_out;
    int attn_in_out = ((long long)out_size >= (long long)OUT_ELEMS + ATTN_ELEMS);

    dim3 blk(256);
    dim3 g_gemm(DMdim / 128, (Bdim * Sdim) / 128);   // (8, 64)

    gemm1024_tf32<1><<<g_gemm, blk>>>(q_in, wq_w, wq_b, qh);
    gemm1024_tf32<1><<<g_gemm, blk>>>(k_in, wk_w, wk_b, kh);
    gemm1024_tf32<1><<<g_gemm, blk>>>(v_in, wv_w, wv_b, vh);

    if (attn_in_out) {
        float* attn = out + OUT_ELEMS;
        qk_tf32<<<dim3(NCTILE, Sdim/128, BHdim), blk>>>(mask, attn, 0);
        pv_tf32<<<dim3(Sdim/128, BHdim), blk>>>(attn, 0);
    } else {
        for (int c = 0; c < BHdim; c += CHUNK_BH) {
            qk_tf32<<<dim3(NCTILE, Sdim/128, CHUNK_BH), blk>>>(mask, attn_chunk, c);
            pv_tf32<<<dim3(Sdim/128, CHUNK_BH), blk>>>(attn_chunk, c);
        }
    }

    gemm1024_tf32<0><<<g_gemm, blk>>>(concat, dense_w, dense_b, out);
}